// round 16
// baseline (speedup 1.0000x reference)
#include <cuda_runtime.h>
#include <cuda_fp16.h>
#include <cstdint>
#include <math.h>

#define Tlen 2048
#define Bdim 16
#define Hdim 1024
#define NLay 4
#define N3H  3072
#define Mrows (Tlen * Bdim)      // 32768

// ---------------- device scratch (no allocs allowed) ----------------
__device__ __half g_Uh [(size_t)Mrows * N3H];       // U = x @ W_l (fp16)
__device__ float  g_X0 [(size_t)Mrows * Hdim];      // fp32 x ping (highway)
__device__ float  g_X1 [(size_t)Mrows * Hdim];      // fp32 x pong
__device__ __half g_Xh0[(size_t)Mrows * Hdim];      // fp16 x ping (GEMM A)
__device__ __half g_Xh1[(size_t)Mrows * Hdim];      // fp16 x pong
__device__ __half g_Wh [(size_t)3 * Hdim * N3H];    // fp16 W[1..3]
__device__ float  g_U0p[8 * N3H];                    // layer-0 gemv partials (fp32)

// ---------------- PTX helpers ----------------
__device__ __forceinline__ uint32_t smem_u32(const void* p) {
    uint32_t a;
    asm("{ .reg .u64 t; cvta.to.shared.u64 t, %1; cvt.u32.u64 %0, t; }" : "=r"(a) : "l"(p));
    return a;
}
#define CP_ASYNC16(dst, src) \
    asm volatile("cp.async.cg.shared.global [%0], [%1], 16;" :: "r"(dst), "l"(src) : "memory")
#define CP_COMMIT()   asm volatile("cp.async.commit_group;" ::: "memory")
#define CP_WAIT(n)    asm volatile("cp.async.wait_group %0;" :: "n"(n) : "memory")

#define LDSM_X4(r0, r1, r2, r3, a) \
    asm volatile("ldmatrix.sync.aligned.m8n8.x4.shared.b16 {%0,%1,%2,%3}, [%4];" \
                 : "=r"(r0), "=r"(r1), "=r"(r2), "=r"(r3) : "r"(a))
#define LDSM_X4_T(r0, r1, r2, r3, a) \
    asm volatile("ldmatrix.sync.aligned.m8n8.x4.trans.shared.b16 {%0,%1,%2,%3}, [%4];" \
                 : "=r"(r0), "=r"(r1), "=r"(r2), "=r"(r3) : "r"(a))

__device__ __forceinline__ void mma_f16(float* d, const uint32_t* a, const uint32_t* b) {
    asm volatile(
        "mma.sync.aligned.m16n8k16.row.col.f32.f16.f16.f32 "
        "{%0,%1,%2,%3}, {%4,%5,%6,%7}, {%8,%9}, {%0,%1,%2,%3};"
        : "+f"(d[0]), "+f"(d[1]), "+f"(d[2]), "+f"(d[3])
        : "r"(a[0]), "r"(a[1]), "r"(a[2]), "r"(a[3]), "r"(b[0]), "r"(b[1]));
}

// Single-MUFU tanh (sm_75+).
__device__ __forceinline__ float tanh_approx(float x) {
    float y;
    asm("tanh.approx.f32 %0, %1;" : "=f"(y) : "f"(x));
    return y;
}

// ---------------- W -> fp16 for layers 1..3 ----------------
__global__ void round_wh(const float* __restrict__ W, __half* __restrict__ Wh) {
    const size_t i = (size_t)blockIdx.x * 256 + threadIdx.x;
    Wh[i] = __float2half_rn(W[(size_t)Hdim * N3H + i]);
}

// ---------------- layer-0 GEMV partials (fp32) ----------------
__global__ void gemv_partial(const float* __restrict__ inp, const float* __restrict__ W0) {
    const int k = blockIdx.x * 128 + threadIdx.x;
    const int h0 = blockIdx.y * 128;
    float s = 0.f;
#pragma unroll 8
    for (int h = 0; h < 128; h++)
        s = fmaf(inp[h0 + h], W0[(size_t)(h0 + h) * N3H + k], s);
    g_U0p[blockIdx.y * N3H + k] = s;
}

// ---------------- fp16 mma.sync GEMM: 4-stage pipeline, K-chunk 32 ----------
// C[M,N] = A[M,K] * B[K,N];  M=32768, N=3072, K=1024; A,B,C fp16 (fp32 accum).
#define NSTG  4
#define A_ST  40                  // halfs per A smem row (32 + 8 pad) = 80 B
#define B_ST  136                 // halfs per B smem row (128 + 8 pad) = 272 B
#define A_STG (128 * A_ST)        // 5120 halfs per stage
#define B_STG (32 * B_ST)         // 4352 halfs per stage
#define GEMM_SMEM (NSTG * (A_STG + B_STG) * 2)   // 75776 bytes
#define KCH   32                  // 1024 / 32

__global__ void __launch_bounds__(256, 2) gemm_f16mma(
    const __half* __restrict__ A, const __half* __restrict__ B, __half* __restrict__ C)
{
    extern __shared__ __half sm[];
    __half* As = sm;                      // [NSTG][128][40]
    __half* Bs = sm + NSTG * A_STG;       // [NSTG][32][136]
    const uint32_t sbA = smem_u32(As);
    const uint32_t sbB = smem_u32(Bs);

    const int tid = threadIdx.x;
    const int n0 = blockIdx.x * 128;
    const int m0 = blockIdx.y * 128;
    const int wid = tid >> 5, lane = tid & 31;
    const int wm = wid & 1, wn = wid >> 1;
    const int g = lane >> 2, tg = lane & 3;

    const __half* Ag = A + (size_t)m0 * 1024;
    const __half* Bg = B + n0;

    auto load_chunk = [&](int kc, int s) {
        const int koff = kc * 32;
        // A: 128 rows x 32 halfs (4 x 16B/row) = 512 transfers / 256 thr
#pragma unroll
        for (int i = 0; i < 2; i++) {
            const int idx = i * 256 + tid;
            const int row = idx >> 2, c16 = idx & 3;
            CP_ASYNC16(sbA + (s * A_STG + row * A_ST + c16 * 8) * 2,
                       Ag + (size_t)row * 1024 + koff + c16 * 8);
        }
        // B: 32 rows x 128 halfs (16 x 16B/row) = 512 transfers / 256 thr
#pragma unroll
        for (int i = 0; i < 2; i++) {
            const int idx = i * 256 + tid;
            const int row = idx >> 4, c16 = idx & 15;
            CP_ASYNC16(sbB + (s * B_STG + row * B_ST + c16 * 8) * 2,
                       Bg + (size_t)(koff + row) * N3H + c16 * 8);
        }
        CP_COMMIT();
    };

    const int a_row = wm * 64 + (lane & 15);
    const int a_kof = (lane >> 4) * 8;
    const int b_krow = (lane & 7) + ((lane >> 3) & 1) * 8;
    const int b_ncol = (lane >> 4) * 8;

    float acc[4][4][4];
#pragma unroll
    for (int i = 0; i < 4; i++)
#pragma unroll
        for (int j = 0; j < 4; j++)
#pragma unroll
            for (int q = 0; q < 4; q++) acc[i][j][q] = 0.f;

    load_chunk(0, 0); load_chunk(1, 1); load_chunk(2, 2);

    for (int c = 0; c < KCH; c++) {
        const int s = c & 3;
        // chunk c must be complete; allow the 2 youngest commits to remain in flight
        if (c < KCH - 2)       { CP_WAIT(2); }
        else if (c == KCH - 2) { CP_WAIT(1); }
        else                   { CP_WAIT(0); }
        // single barrier: data-ready convergence + write-hazard guard for the
        // stage that load_chunk(c+3) below will overwrite (stage of chunk c-1,
        // whose compute all warps finished before reaching this barrier).
        __syncthreads();

#pragma unroll
        for (int ks = 0; ks < 2; ks++) {
            const int kb = ks * 16;
            uint32_t af[4][4], bf[4][2];
#pragma unroll
            for (int mt = 0; mt < 4; mt++) {
                const uint32_t addr = sbA +
                    (s * A_STG + (a_row + mt * 16) * A_ST + kb + a_kof) * 2;
                LDSM_X4(af[mt][0], af[mt][1], af[mt][2], af[mt][3], addr);
            }
#pragma unroll
            for (int nh = 0; nh < 2; nh++) {
                const uint32_t addr = sbB +
                    (s * B_STG + (kb + b_krow) * B_ST + wn * 32 + nh * 16 + b_ncol) * 2;
                LDSM_X4_T(bf[nh * 2][0], bf[nh * 2][1], bf[nh * 2 + 1][0], bf[nh * 2 + 1][1], addr);
            }
#pragma unroll
            for (int mt = 0; mt < 4; mt++)
#pragma unroll
                for (int nt = 0; nt < 4; nt++)
                    mma_f16(acc[mt][nt], af[mt], bf[nt]);
        }

        if (c + 3 < KCH) load_chunk(c + 3, (c + 3) & 3);
    }

    // fp16 epilogue
#pragma unroll
    for (int mt = 0; mt < 4; mt++) {
        const int row = m0 + wm * 64 + mt * 16 + g;
        __half* Cp0 = C + (size_t)row * N3H + n0 + wn * 32 + 2 * tg;
        __half* Cp1 = Cp0 + (size_t)8 * N3H;
#pragma unroll
        for (int nt = 0; nt < 4; nt++) {
            *(__half2*)(Cp0 + nt * 8) = __floats2half2_rn(acc[mt][nt][0], acc[mt][nt][1]);
            *(__half2*)(Cp1 + nt * 8) = __floats2half2_rn(acc[mt][nt][2], acc[mt][nt][3]);
        }
    }
}

// ---------------- SRU scan (layers 1..3), fp16 U, tanh gates ----------------
#define UF 8
template <bool FINAL>
__global__ void __launch_bounds__(128) scan_pipelined(
    const __half* __restrict__ U, const float* __restrict__ Xin,
    const float* __restrict__ c0,
    const float* __restrict__ Vl, const float* __restrict__ bl,
    float* __restrict__ out, __half* __restrict__ outh)
{
    const int idx = blockIdx.x * 128 + threadIdx.x;   // < B*H
    const int b = idx >> 10;
    const int h = idx & 1023;

    float c  = c0[idx];
    const float hvf = 0.5f * Vl[h],        hvr = 0.5f * Vl[Hdim + h];
    const float hbf = 0.5f * bl[h],        hbr = 0.5f * bl[Hdim + h];

    const __half* Ub = U   + (size_t)b * N3H + h;
    const float*  Xb = Xin + (size_t)b * Hdim + h;

    float p1b[2][UF], p2b[2][UF], sub[2][UF], sxb[2][UF];

#define LOAD_BATCH(S, T0) do {                                               \
    _Pragma("unroll")                                                        \
    for (int i = 0; i < UF; i++) {                                           \
        const size_t tu = (size_t)((T0) + i) * (Bdim * N3H);                 \
        sub[S][i] = 0.5f * __half2float(__ldg(Ub + tu));                     \
        p1b[S][i] = fmaf(0.5f, __half2float(__ldg(Ub + tu + Hdim)), hbf);    \
        p2b[S][i] = fmaf(0.5f, __half2float(__ldg(Ub + tu + 2 * Hdim)), hbr);\
        sxb[S][i] = 0.5f * __ldg(Xb + (size_t)((T0) + i) * (Bdim * Hdim));   \
    }                                                                        \
} while (0)

#define COMPUTE_BATCH(S, T0) do {                                            \
    _Pragma("unroll")                                                        \
    for (int i = 0; i < UF; i++) {                                           \
        const int t = (T0) + i;                                              \
        const float Tf = tanh_approx(fmaf(hvf, c, p1b[S][i]));               \
        const float Af = fmaf(0.5f, c,  sub[S][i]);                          \
        const float Bf = fmaf(0.5f, c, -sub[S][i]);                          \
        c = fmaf(Tf, Bf, Af);                                                \
        const float Tr = tanh_approx(fmaf(hvr, c, p2b[S][i]));               \
        const float Ar = fmaf(0.5f, c,  sxb[S][i]);                          \
        const float Br = fmaf(0.5f, c, -sxb[S][i]);                          \
        const float hv = fmaf(Tr, Br, Ar);                                   \
        const size_t oidx = FINAL ? ((size_t)b * Tlen + t) * Hdim + h        \
                                  : ((size_t)t * Bdim + b) * Hdim + h;       \
        out[oidx] = hv;                                                      \
        if (!FINAL) outh[oidx] = __float2half_rn(hv);                        \
    }                                                                        \
} while (0)

    LOAD_BATCH(0, 0);
    for (int t0 = 0; t0 < Tlen; t0 += 2 * UF) {
        LOAD_BATCH(1, t0 + UF);
        COMPUTE_BATCH(0, t0);
        if (t0 + 2 * UF < Tlen) LOAD_BATCH(0, t0 + 2 * UF);
        COMPUTE_BATCH(1, t0 + UF);
    }
#undef LOAD_BATCH
#undef COMPUTE_BATCH
}

// ---------------- layer-0 scan: broadcast inputs, tanh gates ----------------
__global__ void __launch_bounds__(128) scan_l0(
    const float* __restrict__ U0p, const float* __restrict__ inp,
    const float* __restrict__ c0,
    const float* __restrict__ Vl, const float* __restrict__ bl,
    float* __restrict__ out, __half* __restrict__ outh)
{
    const int idx = blockIdx.x * 128 + threadIdx.x;
    const int b = idx >> 10;
    const int h = idx & 1023;

    float c  = c0[idx];
    const float hvf = 0.5f * Vl[h],  hvr = 0.5f * Vl[Hdim + h];
    const float hbf = 0.5f * bl[h],  hbr = 0.5f * bl[Hdim + h];

    float u0 = 0.f, u1 = 0.f, u2 = 0.f;
#pragma unroll
    for (int p = 0; p < 8; p++) {
        u0 += U0p[p * N3H + h];
        u1 += U0p[p * N3H + Hdim + h];
        u2 += U0p[p * N3H + 2 * Hdim + h];
    }
    const float su = 0.5f * u0;
    const float p1 = fmaf(0.5f, u1, hbf);
    const float p2 = fmaf(0.5f, u2, hbr);
    const float sx = 0.5f * inp[h];

#pragma unroll 8
    for (int t = 0; t < Tlen; t++) {
        const float Tf = tanh_approx(fmaf(hvf, c, p1));
        const float Af = fmaf(0.5f, c,  su);
        const float Bf = fmaf(0.5f, c, -su);
        c = fmaf(Tf, Bf, Af);
        const float Tr = tanh_approx(fmaf(hvr, c, p2));
        const float Ar = fmaf(0.5f, c,  sx);
        const float Br = fmaf(0.5f, c, -sx);
        const float hv = fmaf(Tr, Br, Ar);
        const size_t oidx = ((size_t)t * Bdim + b) * Hdim + h;
        out[oidx] = hv;
        outh[oidx] = __float2half_rn(hv);
    }
}

// ---------------------------------------------------------------------------
extern "C" void kernel_launch(void* const* d_in, const int* in_sizes, int n_in,
                              void* d_out, int out_size)
{
    const float* c_n  = (const float*)d_in[0];
    const float* inp  = (const float*)d_in[2];
    const float* W    = (const float*)d_in[3];
    const float* V    = (const float*)d_in[4];
    const float* bias = (const float*)d_in[5];
    float* out = (float*)d_out;

    float *pX0, *pX1, *pU0p;
    __half *pUh, *pXh0, *pXh1, *pWh;
    cudaGetSymbolAddress((void**)&pUh,  g_Uh);
    cudaGetSymbolAddress((void**)&pX0,  g_X0);
    cudaGetSymbolAddress((void**)&pX1,  g_X1);
    cudaGetSymbolAddress((void**)&pXh0, g_Xh0);
    cudaGetSymbolAddress((void**)&pXh1, g_Xh1);
    cudaGetSymbolAddress((void**)&pWh,  g_Wh);
    cudaGetSymbolAddress((void**)&pU0p, g_U0p);

    cudaFuncSetAttribute(gemm_f16mma, cudaFuncAttributeMaxDynamicSharedMemorySize, GEMM_SMEM);

    // launch 0
    round_wh<<<(3 * Hdim * N3H) / 256, 256>>>(W, pWh);
    // launch 1
    gemv_partial<<<dim3(N3H / 128, 8), 128>>>(inp, W);
    // launch 2
    scan_l0<<<(Bdim * Hdim) / 128, 128>>>(pU0p, inp, c_n, V, bias, pX0, pXh0);

    const float*  xin  = pX0;
    const __half* xinh = pXh0;
    float*  xout  = pX1;
    __half* xouth = pXh1;
    for (int l = 1; l < NLay; l++) {
        // launches 3, 5, 7 — ncu -s 5 lands on the l=2 GEMM
        gemm_f16mma<<<dim3(N3H / 128, Mrows / 128), 256, GEMM_SMEM>>>(
            xinh, pWh + (size_t)(l - 1) * Hdim * N3H, pUh);
        const float* Vl = V + (size_t)l * 2 * Hdim;
        const float* bl = bias + (size_t)l * 2 * Hdim;
        if (l == NLay - 1) {
            scan_pipelined<true><<<(Bdim * Hdim) / 128, 128>>>(pUh, xin, c_n, Vl, bl, out, nullptr);
        } else {
            scan_pipelined<false><<<(Bdim * Hdim) / 128, 128>>>(pUh, xin, c_n, Vl, bl, xout, xouth);
            const float* t;
            t = xin; xin = xout; xout = (float*)t;
            const __half* th;
            th = xinh; xinh = xouth; xouth = (__half*)th;
        }
    }
}